// round 15
// baseline (speedup 1.0000x reference)
#include <cuda_runtime.h>
#include <cuda_bf16.h>
#include <math.h>
#include <stdint.h>

// Problem constants (B=2, T=2048, D=1024, H=16, hd=64)
#define BT 4096
#define DMODEL 1024
#define D3 3072
#define NHEAD 16
#define HD 64
#define TQ 2048

// Scratch (device globals: runtime allocation is forbidden).
__device__ float g_qkv[(size_t)BT * D3];     // 48 MB
__device__ float g_cos_tab[TQ * 32];
__device__ float g_sin_tab[TQ * 32];
// Per-head interleaved hi/lo bf16 K and V (256 B per (t) row).
__device__ __nv_bfloat16 g_ki[(size_t)32 * 2048 * 128];  // 16 MB
__device__ __nv_bfloat16 g_vi[(size_t)32 * 2048 * 128];  // 16 MB
// Interleaved [hi16|lo16] bf16 GEMM operands.
__device__ __nv_bfloat16 g_xi[(size_t)BT * 2 * DMODEL];      // 16 MB
__device__ __nv_bfloat16 g_wqi[(size_t)D3 * 2 * DMODEL];     // 12 MB
__device__ __nv_bfloat16 g_woi[(size_t)DMODEL * 2 * DMODEL]; // 4 MB
__device__ __nv_bfloat16 g_atti[(size_t)BT * 2 * DMODEL];    // 16 MB

// ---------------------------------------------------------------------------
// Pre-fill of g_qkv (kept from the first passing round, insurance).
// ---------------------------------------------------------------------------
__global__ __launch_bounds__(256) void fill_qkv_kernel()
{
    size_t n = (size_t)BT * D3;
    for (size_t i = blockIdx.x * 256ull + threadIdx.x; i < n;
         i += (size_t)gridDim.x * 256ull)
        g_qkv[i] = 0.05f;
}

// ---------------------------------------------------------------------------
// RoPE tables.
// ---------------------------------------------------------------------------
__global__ __launch_bounds__(256) void rope_table_kernel()
{
    int idx = blockIdx.x * 256 + threadIdx.x;
    if (idx >= TQ * 32) return;
    int t = idx >> 5, f = idx & 31;
    float invf = (float)exp((double)f * (-9.210340371976184 / 32.0));
    float ang = (float)t * invf;
    g_cos_tab[idx] = (float)cos((double)ang);
    g_sin_tab[idx] = (float)sin((double)ang);
}

// ---------------------------------------------------------------------------
// Helpers
// ---------------------------------------------------------------------------
__device__ __forceinline__ uint32_t sptr(const void* p)
{
    return (uint32_t)__cvta_generic_to_shared(p);
}
__device__ __forceinline__ void ldsm4(uint32_t* r, uint32_t addr)
{
    asm volatile("ldmatrix.sync.aligned.m8n8.x4.shared.b16 {%0,%1,%2,%3}, [%4];"
                 : "=r"(r[0]), "=r"(r[1]), "=r"(r[2]), "=r"(r[3]) : "r"(addr));
}
__device__ __forceinline__ void ldsm4t(uint32_t* r, uint32_t addr)
{
    asm volatile("ldmatrix.sync.aligned.m8n8.x4.trans.shared.b16 {%0,%1,%2,%3}, [%4];"
                 : "=r"(r[0]), "=r"(r[1]), "=r"(r[2]), "=r"(r[3]) : "r"(addr));
}
__device__ __forceinline__ void mma16816(float* c, const uint32_t* a,
                                         const uint32_t* b)
{
    asm volatile(
        "mma.sync.aligned.m16n8k16.row.col.f32.bf16.bf16.f32 "
        "{%0,%1,%2,%3}, {%4,%5,%6,%7}, {%8,%9}, {%0,%1,%2,%3};"
        : "+f"(c[0]), "+f"(c[1]), "+f"(c[2]), "+f"(c[3])
        : "r"(a[0]), "r"(a[1]), "r"(a[2]), "r"(a[3]), "r"(b[0]), "r"(b[1]));
}
__device__ __forceinline__ void pack_hl(float x, float y,
                                        uint32_t& hi, uint32_t& lo)
{
    __nv_bfloat16 xh = __float2bfloat16(x);
    __nv_bfloat16 yh = __float2bfloat16(y);
    __nv_bfloat162 h2 = {xh, yh};
    __nv_bfloat162 l2 = {__float2bfloat16(x - __bfloat162float(xh)),
                         __float2bfloat16(y - __bfloat162float(yh))};
    hi = *(uint32_t*)&h2;
    lo = *(uint32_t*)&l2;
}
__device__ __forceinline__ void cpa16(uint32_t smem, const void* g)
{
    asm volatile("cp.async.cg.shared.global [%0], [%1], 16;"
                 :: "r"(smem), "l"(g));
}

// ---------------------------------------------------------------------------
// One-time fp32 -> interleaved [hi16|lo16] bf16 (16-elem groups).
// dst_sel: 0=g_xi 1=g_wqi 2=g_woi.
// ---------------------------------------------------------------------------
__global__ __launch_bounds__(256) void conv_hl_kernel(
    const float* __restrict__ src, int dst_sel, size_t n)
{
    __nv_bfloat16* dst = (dst_sel == 0) ? g_xi : (dst_sel == 1) ? g_wqi : g_woi;
    size_t ngroups = n >> 4;
    for (size_t g = blockIdx.x * 256ull + threadIdx.x; g < ngroups;
         g += (size_t)gridDim.x * 256ull) {
        const float4* s4 = (const float4*)(src + g * 16);
        uint32_t h[8], l[8];
#pragma unroll
        for (int j = 0; j < 4; j++) {
            float4 v = s4[j];
            pack_hl(v.x, v.y, h[2 * j], l[2 * j]);
            pack_hl(v.z, v.w, h[2 * j + 1], l[2 * j + 1]);
        }
        uint4* d = (uint4*)(dst + g * 32);
        d[0] = make_uint4(h[0], h[1], h[2], h[3]);
        d[1] = make_uint4(h[4], h[5], h[6], h[7]);
        d[2] = make_uint4(l[0], l[1], l[2], l[3]);
        d[3] = make_uint4(l[4], l[5], l[6], l[7]);
    }
}

// ---------------------------------------------------------------------------
// Fused RoPE + KV convert. One block per (b,t) row.
//  - q (cols 0..1023): rotate, write back to g_qkv (fp32).
//  - k (cols 1024..2047): rotate, split hi/lo, write to g_ki ONLY.
//  - v (cols 2048..3071): split hi/lo, write to g_vi.
// Same fp32 values as the old rope+kv_conv pair -> bit-identical outputs.
// ---------------------------------------------------------------------------
__global__ __launch_bounds__(256) void rope_kv_kernel()
{
    __shared__ float s[2048];
    __shared__ float cs[32], sn[32];
    const int row = blockIdx.x;
    const int b = row >> 11, t = row & 2047;
    float* base = g_qkv + (size_t)row * D3;

    if (threadIdx.x < 32) {
        cs[threadIdx.x] = g_cos_tab[t * 32 + threadIdx.x];
        sn[threadIdx.x] = g_sin_tab[t * 32 + threadIdx.x];
    }
    for (int j = threadIdx.x; j < 2048; j += 256) s[j] = base[j];
    __syncthreads();
#pragma unroll
    for (int jj = 0; jj < 8; jj++) {
        int j = threadIdx.x + jj * 256;
        int i = j & (HD - 1);
        int hb = j - i;
        int f = i & 31;
        float self = s[j];
        float val;
        if (i < 32) val = self * cs[f] - s[hb + 2 * i + 1] * sn[f];
        else        val = self * cs[f] + s[hb + 2 * (i - 32)] * sn[f];
        if (j < 1024) {
            base[j] = val;                      // q back to g_qkv
        } else {
            int d4 = j - 1024;                  // k -> g_ki (hi/lo)
            int h = d4 >> 6, d = d4 & 63;
            size_t ob = ((size_t)(b * 16 + h) * 2048 + t) * 128;
            __nv_bfloat16 hi = __float2bfloat16(val);
            g_ki[ob + d] = hi;
            g_ki[ob + 64 + d] = __float2bfloat16(val - __bfloat162float(hi));
        }
    }
    // v -> g_vi
#pragma unroll
    for (int jj = 0; jj < 4; jj++) {
        int j = threadIdx.x + jj * 256;         // 0..1023
        float val = base[2048 + j];
        int h = j >> 6, d = j & 63;
        size_t ob = ((size_t)(b * 16 + h) * 2048 + t) * 128;
        __nv_bfloat16 hi = __float2bfloat16(val);
        g_vi[ob + d] = hi;
        g_vi[ob + 64 + d] = __float2bfloat16(val - __bfloat162float(hi));
    }
}

// ---------------------------------------------------------------------------
// bf16-split tensor GEMM NT on pre-converted interleaved operands,
// SOFTWARE-PIPELINED: prefetch tile k+1 into regs BEFORE compute(k) so the
// LDG latency hides under the mma work (R13's order exposed it each tile).
// CTA 128x128, BK=16 fp32, 8 warps (2x4), warp tile 64x32, 20KB smem,
// 2 CTA/SM. Fragment math bit-identical to R11/R13.
// a_sel: 0=g_xi 1=g_atti.  b_sel: 0=g_wqi 1=g_woi.  c_gqkv: C = g_qkv.
// ---------------------------------------------------------------------------
#define KST2 40   // bf16 elems per smem row (32 data + 8 pad) = 80 B

__global__ __launch_bounds__(256, 2) void gemm_i3p(
    const float* __restrict__ bias, float* __restrict__ Cp,
    int M, int N, int K, int a_sel, int b_sel, int c_gqkv)
{
    const __nv_bfloat16* Ai = a_sel ? g_atti : g_xi;
    const __nv_bfloat16* Bi = b_sel ? g_woi : g_wqi;
    float* C = c_gqkv ? (float*)g_qkv : Cp;
    const int K2 = 2 * K;

    __shared__ __align__(16) __nv_bfloat16 As[128 * KST2];
    __shared__ __align__(16) __nv_bfloat16 Bs[128 * KST2];

    const int tid = threadIdx.x;
    const int lane = tid & 31, warp = tid >> 5;
    const int wm = warp >> 2, wn = warp & 3;
    const int m0 = blockIdx.y * 128, n0 = blockIdx.x * 128;

    const int lrow = tid >> 1;            // 0..127
    const int half = tid & 1;

    float acc[4][4][4];
#pragma unroll
    for (int mt = 0; mt < 4; mt++)
#pragma unroll
        for (int nt = 0; nt < 4; nt++)
#pragma unroll
            for (int i = 0; i < 4; i++) acc[mt][nt][i] = 0.f;

    const int a_row = wm * 64 + (lane & 15);
    uint32_t a_base = sptr(As) +
        (uint32_t)(a_row * KST2 + (lane >> 4) * 8) * 2u;
    const int b_row = wn * 32 + (lane & 7) + ((lane >> 4) & 1) * 8;
    uint32_t b_base = sptr(Bs) +
        (uint32_t)(b_row * KST2 + ((lane >> 3) & 1) * 8) * 2u;

    const uint4* Ag = (const uint4*)(Ai + (size_t)(m0 + lrow) * K2);
    const uint4* Bg = (const uint4*)(Bi + (size_t)(n0 + lrow) * K2);
    uint4* Asm = (uint4*)((char*)As + lrow * 80 + half * 32);
    uint4* Bsm = (uint4*)((char*)Bs + lrow * 80 + half * 32);

    const int NT = K >> 4;
    // Prologue: fetch tile 0.
    int gi = half * 2;
    uint4 pa0 = Ag[gi], pa1 = Ag[gi + 1];
    uint4 pb0 = Bg[gi], pb1 = Bg[gi + 1];

    for (int kt = 0; kt < NT; kt++) {
        __syncthreads();   // previous compute done reading smem
        Asm[0] = pa0; Asm[1] = pa1;
        Bsm[0] = pb0; Bsm[1] = pb1;
        __syncthreads();

        // Prefetch tile kt+1 (independent of compute below -> LDG overlaps).
        if (kt + 1 < NT) {
            gi = (kt + 1) * 4 + half * 2;
            pa0 = Ag[gi]; pa1 = Ag[gi + 1];
            pb0 = Bg[gi]; pb1 = Bg[gi + 1];
        }

        uint32_t bh[4][2], bl[4][2];
#pragma unroll
        for (int ntp = 0; ntp < 2; ntp++) {
            uint32_t ad = b_base + (uint32_t)(ntp * 16 * KST2) * 2u;
            uint32_t t4[4];
            ldsm4(t4, ad);
            bh[2*ntp][0] = t4[0]; bh[2*ntp][1] = t4[1];
            bh[2*ntp+1][0] = t4[2]; bh[2*ntp+1][1] = t4[3];
            ldsm4(t4, ad + 32);
            bl[2*ntp][0] = t4[0]; bl[2*ntp][1] = t4[1];
            bl[2*ntp+1][0] = t4[2]; bl[2*ntp+1][1] = t4[3];
        }
#pragma unroll
        for (int mt = 0; mt < 4; mt++) {
            uint32_t ah[4], al[4];
            uint32_t ad = a_base + (uint32_t)(mt * 16 * KST2) * 2u;
            ldsm4(ah, ad);
            ldsm4(al, ad + 32);
#pragma unroll
            for (int nt = 0; nt < 4; nt++) {
                mma16816(acc[mt][nt], ah, bh[nt]);
                mma16816(acc[mt][nt], al, bh[nt]);
                mma16816(acc[mt][nt], ah, bl[nt]);
            }
        }
    }

    const int g = lane >> 2, cc = (lane & 3) * 2;
#pragma unroll
    for (int mt = 0; mt < 4; mt++) {
#pragma unroll
        for (int nt = 0; nt < 4; nt++) {
            int row = m0 + wm * 64 + mt * 16 + g;
            int col = n0 + wn * 32 + nt * 8 + cc;
            float b0 = bias ? bias[col] : 0.f;
            float b1 = bias ? bias[col + 1] : 0.f;
            float2 v0 = make_float2(acc[mt][nt][0] + b0, acc[mt][nt][1] + b1);
            float2 v1 = make_float2(acc[mt][nt][2] + b0, acc[mt][nt][3] + b1);
            *(float2*)&C[(size_t)row * N + col] = v0;
            *(float2*)&C[(size_t)(row + 8) * N + col] = v1;
        }
    }
}

// ---------------------------------------------------------------------------
// Tensor-core flash attention (R11 loop verbatim); epilogue now writes the
// interleaved [hi16|lo16] g_atti directly (same fp32 values split, so the
// downstream GEMM sees bit-identical operands vs the old att+conv path).
// ---------------------------------------------------------------------------
#define FKST 72
#define FSTG 18432

__global__ __launch_bounds__(128) void flash_tc_kernel()
{
    __shared__ __align__(16) char sm[2 * FSTG];

    const int bh = blockIdx.x, qt = blockIdx.y;
    const int b = bh >> 4, h = bh & 15;
    const float* Qg = g_qkv + (size_t)(b * TQ + qt * 64) * D3 + h * HD;
    const __nv_bfloat16* Ksrc = g_ki + (size_t)bh * 2048 * 128;
    const __nv_bfloat16* Vsrc = g_vi + (size_t)bh * 2048 * 128;

    const int tid = threadIdx.x, lane = tid & 31, warp = tid >> 5;
    const uint32_t smb = sptr(sm);

    for (int f = tid; f < 1024; f += 128) {
        int r = f >> 4, c = (f & 15) * 4;
        float4 v = *(const float4*)&Qg[(size_t)r * D3 + c];
        uint32_t h0, l0, h1, l1;
        pack_hl(v.x * 0.125f, v.y * 0.125f, h0, l0);
        pack_hl(v.z * 0.125f, v.w * 0.125f, h1, l1);
        uint32_t* QHr = (uint32_t*)(sm + r * 144);
        uint32_t* QLr = (uint32_t*)(sm + 9216 + r * 144);
        QHr[(c >> 1)] = h0; QHr[(c >> 1) + 1] = h1;
        QLr[(c >> 1)] = l0; QLr[(c >> 1) + 1] = l1;
    }
    __syncthreads();

    uint32_t qh[4][4], ql[4][4];
    {
        int arow = warp * 16 + (lane & 15);
        int akof = (lane >> 4) * 8;
        uint32_t qa = smb + (uint32_t)(arow * FKST + akof) * 2u;
#pragma unroll
        for (int ks = 0; ks < 4; ks++) {
            ldsm4(qh[ks], qa + ks * 32);
            ldsm4(ql[ks], qa + ks * 32 + 9216);
        }
    }
    __syncthreads();

    uint32_t kfb[2], vfb[2];
    {
        uint32_t ko = (uint32_t)(((lane & 7) + ((lane >> 4) & 1) * 8) * 144 +
                                 ((lane >> 3) & 1) * 16);
        uint32_t vo = 9216u + (uint32_t)((lane & 15) * 144) +
                      ((lane >> 4) & 1) * 16u;
        kfb[0] = smb + ko; kfb[1] = smb + FSTG + ko;
        vfb[0] = smb + vo; vfb[1] = smb + FSTG + vo;
    }

    float m0 = -1e30f, m1 = -1e30f, l0 = 0.f, l1 = 0.f;
    float oacc[8][4];
#pragma unroll
    for (int nt = 0; nt < 8; nt++)
#pragma unroll
        for (int i = 0; i < 4; i++) oacc[nt][i] = 0.f;

    auto fill = [&](int s, int kt) {
        uint32_t sb = smb + s * FSTG;
#pragma unroll
        for (int q = 0; q < 8; q++) {
            int g = tid + q * 128;
            int kv = g >> 9, r = (g >> 4) & 31, c = g & 15;
            const __nv_bfloat16* src =
                (kv ? Vsrc : Ksrc) + ((size_t)(kt * 32 + r)) * 128 + c * 8;
            uint32_t dst = sb + (uint32_t)(kv * 9216) +
                           ((c & 8) ? 4608u : 0u) +
                           (uint32_t)(r * 144) + (uint32_t)((c & 7) * 16);
            cpa16(dst, src);
        }
    };

    fill(0, 0);
    asm volatile("cp.async.commit_group;");

    for (int kt = 0; kt < 64; kt++) {
        const int s = kt & 1;
        if (kt + 1 < 64) fill(s ^ 1, kt + 1);
        asm volatile("cp.async.commit_group;");
        asm volatile("cp.async.wait_group 1;");
        __syncthreads();

        float sacc[4][4];
#pragma unroll
        for (int nt = 0; nt < 4; nt++)
#pragma unroll
            for (int i = 0; i < 4; i++) sacc[nt][i] = 0.f;
#pragma unroll
        for (int ks = 0; ks < 4; ks++) {
#pragma unroll
            for (int ntp = 0; ntp < 2; ntp++) {
                uint32_t ad = kfb[s] + (uint32_t)(ntp * 16 * 144) + ks * 32;
                uint32_t bh4[4], bl4[4];
                ldsm4(bh4, ad);
                ldsm4(bl4, ad + 4608);
                mma16816(sacc[2*ntp],   qh[ks], bh4);
                mma16816(sacc[2*ntp],   ql[ks], bh4);
                mma16816(sacc[2*ntp],   qh[ks], bl4);
                mma16816(sacc[2*ntp+1], qh[ks], bh4 + 2);
                mma16816(sacc[2*ntp+1], ql[ks], bh4 + 2);
                mma16816(sacc[2*ntp+1], qh[ks], bl4 + 2);
            }
        }

        float rm0 = -1e30f, rm1 = -1e30f;
#pragma unroll
        for (int nt = 0; nt < 4; nt++) {
            rm0 = fmaxf(rm0, fmaxf(sacc[nt][0], sacc[nt][1]));
            rm1 = fmaxf(rm1, fmaxf(sacc[nt][2], sacc[nt][3]));
        }
        rm0 = fmaxf(rm0, __shfl_xor_sync(0xffffffffu, rm0, 1));
        rm0 = fmaxf(rm0, __shfl_xor_sync(0xffffffffu, rm0, 2));
        rm1 = fmaxf(rm1, __shfl_xor_sync(0xffffffffu, rm1, 1));
        rm1 = fmaxf(rm1, __shfl_xor_sync(0xffffffffu, rm1, 2));
        float mn0 = fmaxf(m0, rm0), mn1 = fmaxf(m1, rm1);
        float c0 = __expf(m0 - mn0), c1 = __expf(m1 - mn1);
        float p[4][4];
        float s0 = 0.f, s1 = 0.f;
#pragma unroll
        for (int nt = 0; nt < 4; nt++) {
            p[nt][0] = __expf(sacc[nt][0] - mn0);
            p[nt][1] = __expf(sacc[nt][1] - mn0);
            p[nt][2] = __expf(sacc[nt][2] - mn1);
            p[nt][3] = __expf(sacc[nt][3] - mn1);
            s0 += p[nt][0] + p[nt][1];
            s1 += p[nt][2] + p[nt][3];
        }
        s0 += __shfl_xor_sync(0xffffffffu, s0, 1);
        s0 += __shfl_xor_sync(0xffffffffu, s0, 2);
        s1 += __shfl_xor_sync(0xffffffffu, s1, 1);
        s1 += __shfl_xor_sync(0xffffffffu, s1, 2);
        l0 = l0 * c0 + s0; l1 = l1 * c1 + s1;
        m0 = mn0; m1 = mn1;
#pragma unroll
        for (int nt = 0; nt < 8; nt++) {
            oacc[nt][0] *= c0; oacc[nt][1] *= c0;
            oacc[nt][2] *= c1; oacc[nt][3] *= c1;
        }

#pragma unroll
        for (int j = 0; j < 2; j++) {
            uint32_t ph[4], pl[4];
            pack_hl(p[2 * j][0],     p[2 * j][1],     ph[0], pl[0]);
            pack_hl(p[2 * j][2],     p[2 * j][3],     ph[1], pl[1]);
            pack_hl(p[2 * j + 1][0], p[2 * j + 1][1], ph[2], pl[2]);
            pack_hl(p[2 * j + 1][2], p[2 * j + 1][3], ph[3], pl[3]);
#pragma unroll
            for (int ntp = 0; ntp < 4; ntp++) {
                uint32_t ad = vfb[s] + (uint32_t)(j * 16 * 144) + ntp * 32;
                uint32_t vh4[4], vl4[4];
                ldsm4t(vh4, ad);
                ldsm4t(vl4, ad + 4608);
                mma16816(oacc[2*ntp],   ph, vh4);
                mma16816(oacc[2*ntp],   pl, vh4);
                mma16816(oacc[2*ntp],   ph, vl4);
                mma16816(oacc[2*ntp+1], ph, vh4 + 2);
                mma16816(oacc[2*ntp+1], pl, vh4 + 2);
                mma16816(oacc[2*ntp+1], ph, vl4 + 2);
            }
        }
        __syncthreads();
    }

    // Epilogue: normalize and write interleaved hi/lo directly to g_atti.
    // Element (row, col): group g16 = col>>4; hi at row*2048 + g16*32 + (col&15),
    // lo at +16. Thread's two cols are consecutive & even-aligned -> uint32.
    float il0 = 1.f / l0, il1 = 1.f / l1;
    int g = lane >> 2, cc2 = (lane & 3) * 2;
    int row0 = b * TQ + qt * 64 + warp * 16 + g;
#pragma unroll
    for (int nt = 0; nt < 8; nt++) {
        int within = (nt & 1) * 8 + cc2;
        size_t base0 = (size_t)row0 * 2048 +
                       (size_t)(h * 4 + (nt >> 1)) * 32 + within;
        size_t base1 = base0 + (size_t)8 * 2048;
        uint32_t hi, lo;
        pack_hl(oacc[nt][0] * il0, oacc[nt][1] * il0, hi, lo);
        *(uint32_t*)&g_atti[base0] = hi;
        *(uint32_t*)&g_atti[base0 + 16] = lo;
        pack_hl(oacc[nt][2] * il1, oacc[nt][3] * il1, hi, lo);
        *(uint32_t*)&g_atti[base1] = hi;
        *(uint32_t*)&g_atti[base1 + 16] = lo;
    }
}

// ---------------------------------------------------------------------------
extern "C" void kernel_launch(void* const* d_in, const int* in_sizes, int n_in,
                              void* d_out, int out_size)
{
    const float *x = 0, *w_qkv = 0, *w_out = 0, *b_out = 0;
    for (int i = 0; i < n_in; i++) {
        switch (in_sizes[i]) {
            case 4194304: x     = (const float*)d_in[i]; break;
            case 3145728: w_qkv = (const float*)d_in[i]; break;
            case 1048576: w_out = (const float*)d_in[i]; break;
            case 1024:    b_out = (const float*)d_in[i]; break;
        }
    }
    if (!x && n_in >= 4) {
        x     = (const float*)d_in[0];
        w_qkv = (const float*)d_in[1];
        w_out = (const float*)d_in[2];
        b_out = (const float*)d_in[3];
    }
    float* out = (float*)d_out;

    fill_qkv_kernel<<<4096, 256>>>();
    rope_table_kernel<<<(TQ * 32 + 255) / 256, 256>>>();
    // One-time operand conversions.
    conv_hl_kernel<<<1024, 256>>>(x, 0, (size_t)BT * DMODEL);
    conv_hl_kernel<<<1024, 256>>>(w_qkv, 1, (size_t)D3 * DMODEL);
    conv_hl_kernel<<<512, 256>>>(w_out, 2, (size_t)DMODEL * DMODEL);
    // 1) g_qkv = x @ w_qkv^T   (pipelined HMMA GEMM)
    gemm_i3p<<<dim3(D3 / 128, BT / 128), 256>>>(
        nullptr, nullptr, BT, D3, DMODEL, 0, 0, 1);
    // 2) Fused RoPE + KV hi/lo convert
    rope_kv_kernel<<<BT, 256>>>();
    // 3) attention (writes g_atti directly)
    flash_tc_kernel<<<dim3(32, 32), 128>>>();
    // 4) out = att @ w_out^T + b_out
    gemm_i3p<<<dim3(DMODEL / 128, BT / 128), 256>>>(
        b_out, out, BT, DMODEL, DMODEL, 1, 1, 0);
}

// round 16
// speedup vs baseline: 1.0380x; 1.0380x over previous
#include <cuda_runtime.h>
#include <cuda_bf16.h>
#include <math.h>
#include <stdint.h>

// Problem constants (B=2, T=2048, D=1024, H=16, hd=64)
#define BT 4096
#define DMODEL 1024
#define D3 3072
#define NHEAD 16
#define HD 64
#define TQ 2048

// Scratch (device globals: runtime allocation is forbidden).
__device__ float g_qkv[(size_t)BT * D3];     // 48 MB
__device__ float g_att[(size_t)BT * DMODEL]; // 16 MB
__device__ float g_cos_tab[TQ * 32];
__device__ float g_sin_tab[TQ * 32];
// Per-head interleaved hi/lo bf16 K and V (256 B per (t) row).
__device__ __nv_bfloat16 g_ki[(size_t)32 * 2048 * 128];  // 16 MB
__device__ __nv_bfloat16 g_vi[(size_t)32 * 2048 * 128];  // 16 MB

// ---------------------------------------------------------------------------
// Pre-fill of g_qkv (kept from the first passing round, insurance).
// ---------------------------------------------------------------------------
__global__ __launch_bounds__(256) void fill_qkv_kernel()
{
    size_t n = (size_t)BT * D3;
    for (size_t i = blockIdx.x * 256ull + threadIdx.x; i < n;
         i += (size_t)gridDim.x * 256ull)
        g_qkv[i] = 0.05f;
}

// ---------------------------------------------------------------------------
// RoPE tables.
// ---------------------------------------------------------------------------
__global__ __launch_bounds__(256) void rope_table_kernel()
{
    int idx = blockIdx.x * 256 + threadIdx.x;
    if (idx >= TQ * 32) return;
    int t = idx >> 5, f = idx & 31;
    float invf = (float)exp((double)f * (-9.210340371976184 / 32.0));
    float ang = (float)t * invf;
    g_cos_tab[idx] = (float)cos((double)ang);
    g_sin_tab[idx] = (float)sin((double)ang);
}

// ---------------------------------------------------------------------------
// Helpers
// ---------------------------------------------------------------------------
__device__ __forceinline__ uint32_t sptr(const void* p)
{
    return (uint32_t)__cvta_generic_to_shared(p);
}
__device__ __forceinline__ void ldsm4(uint32_t* r, uint32_t addr)
{
    asm volatile("ldmatrix.sync.aligned.m8n8.x4.shared.b16 {%0,%1,%2,%3}, [%4];"
                 : "=r"(r[0]), "=r"(r[1]), "=r"(r[2]), "=r"(r[3]) : "r"(addr));
}
__device__ __forceinline__ void ldsm4t(uint32_t* r, uint32_t addr)
{
    asm volatile("ldmatrix.sync.aligned.m8n8.x4.trans.shared.b16 {%0,%1,%2,%3}, [%4];"
                 : "=r"(r[0]), "=r"(r[1]), "=r"(r[2]), "=r"(r[3]) : "r"(addr));
}
__device__ __forceinline__ void mma16816(float* c, const uint32_t* a,
                                         const uint32_t* b)
{
    asm volatile(
        "mma.sync.aligned.m16n8k16.row.col.f32.bf16.bf16.f32 "
        "{%0,%1,%2,%3}, {%4,%5,%6,%7}, {%8,%9}, {%0,%1,%2,%3};"
        : "+f"(c[0]), "+f"(c[1]), "+f"(c[2]), "+f"(c[3])
        : "r"(a[0]), "r"(a[1]), "r"(a[2]), "r"(a[3]), "r"(b[0]), "r"(b[1]));
}
__device__ __forceinline__ void pack_hl(float x, float y,
                                        uint32_t& hi, uint32_t& lo)
{
    __nv_bfloat16 xh = __float2bfloat16(x);
    __nv_bfloat16 yh = __float2bfloat16(y);
    __nv_bfloat162 h2 = {xh, yh};
    __nv_bfloat162 l2 = {__float2bfloat16(x - __bfloat162float(xh)),
                         __float2bfloat16(y - __bfloat162float(yh))};
    hi = *(uint32_t*)&h2;
    lo = *(uint32_t*)&l2;
}
__device__ __forceinline__ void cpa16(uint32_t smem, const void* g)
{
    asm volatile("cp.async.cg.shared.global [%0], [%1], 16;"
                 :: "r"(smem), "l"(g));
}

// ---------------------------------------------------------------------------
// bf16-split tensor GEMM NT (R11 verbatim - the proven 259us/87us kernel).
// CTA 128x128, BK=16 fp32, 8 warps (2x4), warp tile 64x32, 20KB smem,
// 2 CTA/SM. In-loop fp32->hi/lo conversion.
// a_gatt: A = g_att. c_gqkv: C = g_qkv.
// ---------------------------------------------------------------------------
#define KST2 40   // bf16 elems per smem row (32 data + 8 pad) = 80 B

__global__ __launch_bounds__(256, 2) void gemm_nt_bf16x3(
    const float* __restrict__ Ap, const float* __restrict__ Bp,
    const float* __restrict__ bias, float* __restrict__ Cp,
    int M, int N, int K, int a_gatt, int c_gqkv)
{
    const float* A = a_gatt ? (const float*)g_att : Ap;
    float* C = c_gqkv ? (float*)g_qkv : Cp;

    __shared__ __align__(16) __nv_bfloat16 As[128 * KST2];
    __shared__ __align__(16) __nv_bfloat16 Bs[128 * KST2];

    const int tid = threadIdx.x;
    const int lane = tid & 31, warp = tid >> 5;
    const int wm = warp >> 2, wn = warp & 3;
    const int m0 = blockIdx.y * 128, n0 = blockIdx.x * 128;

    const int lrow = tid >> 1;
    const int lk = (tid & 1) * 8;

    float acc[4][4][4];
#pragma unroll
    for (int mt = 0; mt < 4; mt++)
#pragma unroll
        for (int nt = 0; nt < 4; nt++)
#pragma unroll
            for (int i = 0; i < 4; i++) acc[mt][nt][i] = 0.f;

    const int a_row = wm * 64 + (lane & 15);
    uint32_t a_base = sptr(As) +
        (uint32_t)(a_row * KST2 + (lane >> 4) * 8) * 2u;
    const int b_row = wn * 32 + (lane & 7) + ((lane >> 4) & 1) * 8;
    uint32_t b_base = sptr(Bs) +
        (uint32_t)(b_row * KST2 + ((lane >> 3) & 1) * 8) * 2u;

    uint32_t* Arow32 = (uint32_t*)&As[lrow * KST2];
    uint32_t* Brow32 = (uint32_t*)&Bs[lrow * KST2];
    const int sidx = lk >> 1;

    for (int k0 = 0; k0 < K; k0 += 16) {
        float4 av0 = *(const float4*)&A[(size_t)(m0 + lrow) * K + k0 + lk];
        float4 av1 = *(const float4*)&A[(size_t)(m0 + lrow) * K + k0 + lk + 4];
        float4 bv0 = *(const float4*)&Bp[(size_t)(n0 + lrow) * K + k0 + lk];
        float4 bv1 = *(const float4*)&Bp[(size_t)(n0 + lrow) * K + k0 + lk + 4];
        __syncthreads();
        {
            uint32_t h, l;
            pack_hl(av0.x, av0.y, h, l); Arow32[sidx+0] = h; Arow32[8+sidx+0] = l;
            pack_hl(av0.z, av0.w, h, l); Arow32[sidx+1] = h; Arow32[8+sidx+1] = l;
            pack_hl(av1.x, av1.y, h, l); Arow32[sidx+2] = h; Arow32[8+sidx+2] = l;
            pack_hl(av1.z, av1.w, h, l); Arow32[sidx+3] = h; Arow32[8+sidx+3] = l;
            pack_hl(bv0.x, bv0.y, h, l); Brow32[sidx+0] = h; Brow32[8+sidx+0] = l;
            pack_hl(bv0.z, bv0.w, h, l); Brow32[sidx+1] = h; Brow32[8+sidx+1] = l;
            pack_hl(bv1.x, bv1.y, h, l); Brow32[sidx+2] = h; Brow32[8+sidx+2] = l;
            pack_hl(bv1.z, bv1.w, h, l); Brow32[sidx+3] = h; Brow32[8+sidx+3] = l;
        }
        __syncthreads();

        uint32_t bh[4][2], bl[4][2];
#pragma unroll
        for (int ntp = 0; ntp < 2; ntp++) {
            uint32_t ad = b_base + (uint32_t)(ntp * 16 * KST2) * 2u;
            uint32_t t4[4];
            ldsm4(t4, ad);
            bh[2*ntp][0] = t4[0]; bh[2*ntp][1] = t4[1];
            bh[2*ntp+1][0] = t4[2]; bh[2*ntp+1][1] = t4[3];
            ldsm4(t4, ad + 32);
            bl[2*ntp][0] = t4[0]; bl[2*ntp][1] = t4[1];
            bl[2*ntp+1][0] = t4[2]; bl[2*ntp+1][1] = t4[3];
        }
#pragma unroll
        for (int mt = 0; mt < 4; mt++) {
            uint32_t ah[4], al[4];
            uint32_t ad = a_base + (uint32_t)(mt * 16 * KST2) * 2u;
            ldsm4(ah, ad);
            ldsm4(al, ad + 32);
#pragma unroll
            for (int nt = 0; nt < 4; nt++) {
                mma16816(acc[mt][nt], ah, bh[nt]);
                mma16816(acc[mt][nt], al, bh[nt]);
                mma16816(acc[mt][nt], ah, bl[nt]);
            }
        }
    }

    const int g = lane >> 2, cc = (lane & 3) * 2;
#pragma unroll
    for (int mt = 0; mt < 4; mt++) {
#pragma unroll
        for (int nt = 0; nt < 4; nt++) {
            int row = m0 + wm * 64 + mt * 16 + g;
            int col = n0 + wn * 32 + nt * 8 + cc;
            float b0 = bias ? bias[col] : 0.f;
            float b1 = bias ? bias[col + 1] : 0.f;
            float2 v0 = make_float2(acc[mt][nt][0] + b0, acc[mt][nt][1] + b1);
            float2 v1 = make_float2(acc[mt][nt][2] + b0, acc[mt][nt][3] + b1);
            *(float2*)&C[(size_t)row * N + col] = v0;
            *(float2*)&C[(size_t)(row + 8) * N + col] = v1;
        }
    }
}

// ---------------------------------------------------------------------------
// Fused RoPE + KV convert (proven in R15, identical rel_err).
//  - q: rotate, write back to g_qkv (fp32).
//  - k: rotate, split hi/lo -> g_ki only.
//  - v: split hi/lo -> g_vi.
// ---------------------------------------------------------------------------
__global__ __launch_bounds__(256) void rope_kv_kernel()
{
    __shared__ float s[2048];
    __shared__ float cs[32], sn[32];
    const int row = blockIdx.x;
    const int b = row >> 11, t = row & 2047;
    float* base = g_qkv + (size_t)row * D3;

    if (threadIdx.x < 32) {
        cs[threadIdx.x] = g_cos_tab[t * 32 + threadIdx.x];
        sn[threadIdx.x] = g_sin_tab[t * 32 + threadIdx.x];
    }
    for (int j = threadIdx.x; j < 2048; j += 256) s[j] = base[j];
    __syncthreads();
#pragma unroll
    for (int jj = 0; jj < 8; jj++) {
        int j = threadIdx.x + jj * 256;
        int i = j & (HD - 1);
        int hb = j - i;
        int f = i & 31;
        float self = s[j];
        float val;
        if (i < 32) val = self * cs[f] - s[hb + 2 * i + 1] * sn[f];
        else        val = self * cs[f] + s[hb + 2 * (i - 32)] * sn[f];
        if (j < 1024) {
            base[j] = val;                      // q back to g_qkv
        } else {
            int d4 = j - 1024;                  // k -> g_ki (hi/lo)
            int h = d4 >> 6, d = d4 & 63;
            size_t ob = ((size_t)(b * 16 + h) * 2048 + t) * 128;
            __nv_bfloat16 hi = __float2bfloat16(val);
            g_ki[ob + d] = hi;
            g_ki[ob + 64 + d] = __float2bfloat16(val - __bfloat162float(hi));
        }
    }
    // v -> g_vi
#pragma unroll
    for (int jj = 0; jj < 4; jj++) {
        int j = threadIdx.x + jj * 256;
        float val = base[2048 + j];
        int h = j >> 6, d = j & 63;
        size_t ob = ((size_t)(b * 16 + h) * 2048 + t) * 128;
        __nv_bfloat16 hi = __float2bfloat16(val);
        g_vi[ob + d] = hi;
        g_vi[ob + 64 + d] = __float2bfloat16(val - __bfloat162float(hi));
    }
}

// ---------------------------------------------------------------------------
// Tensor-core flash attention (R11 verbatim).
// ---------------------------------------------------------------------------
#define FKST 72
#define FSTG 18432

__global__ __launch_bounds__(128) void flash_tc_kernel()
{
    __shared__ __align__(16) char sm[2 * FSTG];

    const int bh = blockIdx.x, qt = blockIdx.y;
    const int b = bh >> 4, h = bh & 15;
    const float* Qg = g_qkv + (size_t)(b * TQ + qt * 64) * D3 + h * HD;
    const __nv_bfloat16* Ksrc = g_ki + (size_t)bh * 2048 * 128;
    const __nv_bfloat16* Vsrc = g_vi + (size_t)bh * 2048 * 128;

    const int tid = threadIdx.x, lane = tid & 31, warp = tid >> 5;
    const uint32_t smb = sptr(sm);

    for (int f = tid; f < 1024; f += 128) {
        int r = f >> 4, c = (f & 15) * 4;
        float4 v = *(const float4*)&Qg[(size_t)r * D3 + c];
        uint32_t h0, l0, h1, l1;
        pack_hl(v.x * 0.125f, v.y * 0.125f, h0, l0);
        pack_hl(v.z * 0.125f, v.w * 0.125f, h1, l1);
        uint32_t* QHr = (uint32_t*)(sm + r * 144);
        uint32_t* QLr = (uint32_t*)(sm + 9216 + r * 144);
        QHr[(c >> 1)] = h0; QHr[(c >> 1) + 1] = h1;
        QLr[(c >> 1)] = l0; QLr[(c >> 1) + 1] = l1;
    }
    __syncthreads();

    uint32_t qh[4][4], ql[4][4];
    {
        int arow = warp * 16 + (lane & 15);
        int akof = (lane >> 4) * 8;
        uint32_t qa = smb + (uint32_t)(arow * FKST + akof) * 2u;
#pragma unroll
        for (int ks = 0; ks < 4; ks++) {
            ldsm4(qh[ks], qa + ks * 32);
            ldsm4(ql[ks], qa + ks * 32 + 9216);
        }
    }
    __syncthreads();

    uint32_t kfb[2], vfb[2];
    {
        uint32_t ko = (uint32_t)(((lane & 7) + ((lane >> 4) & 1) * 8) * 144 +
                                 ((lane >> 3) & 1) * 16);
        uint32_t vo = 9216u + (uint32_t)((lane & 15) * 144) +
                      ((lane >> 4) & 1) * 16u;
        kfb[0] = smb + ko; kfb[1] = smb + FSTG + ko;
        vfb[0] = smb + vo; vfb[1] = smb + FSTG + vo;
    }

    float m0 = -1e30f, m1 = -1e30f, l0 = 0.f, l1 = 0.f;
    float oacc[8][4];
#pragma unroll
    for (int nt = 0; nt < 8; nt++)
#pragma unroll
        for (int i = 0; i < 4; i++) oacc[nt][i] = 0.f;

    auto fill = [&](int s, int kt) {
        uint32_t sb = smb + s * FSTG;
#pragma unroll
        for (int q = 0; q < 8; q++) {
            int g = tid + q * 128;
            int kv = g >> 9, r = (g >> 4) & 31, c = g & 15;
            const __nv_bfloat16* src =
                (kv ? Vsrc : Ksrc) + ((size_t)(kt * 32 + r)) * 128 + c * 8;
            uint32_t dst = sb + (uint32_t)(kv * 9216) +
                           ((c & 8) ? 4608u : 0u) +
                           (uint32_t)(r * 144) + (uint32_t)((c & 7) * 16);
            cpa16(dst, src);
        }
    };

    fill(0, 0);
    asm volatile("cp.async.commit_group;");

    for (int kt = 0; kt < 64; kt++) {
        const int s = kt & 1;
        if (kt + 1 < 64) fill(s ^ 1, kt + 1);
        asm volatile("cp.async.commit_group;");
        asm volatile("cp.async.wait_group 1;");
        __syncthreads();

        float sacc[4][4];
#pragma unroll
        for (int nt = 0; nt < 4; nt++)
#pragma unroll
            for (int i = 0; i < 4; i++) sacc[nt][i] = 0.f;
#pragma unroll
        for (int ks = 0; ks < 4; ks++) {
#pragma unroll
            for (int ntp = 0; ntp < 2; ntp++) {
                uint32_t ad = kfb[s] + (uint32_t)(ntp * 16 * 144) + ks * 32;
                uint32_t bh4[4], bl4[4];
                ldsm4(bh4, ad);
                ldsm4(bl4, ad + 4608);
                mma16816(sacc[2*ntp],   qh[ks], bh4);
                mma16816(sacc[2*ntp],   ql[ks], bh4);
                mma16816(sacc[2*ntp],   qh[ks], bl4);
                mma16816(sacc[2*ntp+1], qh[ks], bh4 + 2);
                mma16816(sacc[2*ntp+1], ql[ks], bh4 + 2);
                mma16816(sacc[2*ntp+1], qh[ks], bl4 + 2);
            }
        }

        float rm0 = -1e30f, rm1 = -1e30f;
#pragma unroll
        for (int nt = 0; nt < 4; nt++) {
            rm0 = fmaxf(rm0, fmaxf(sacc[nt][0], sacc[nt][1]));
            rm1 = fmaxf(rm1, fmaxf(sacc[nt][2], sacc[nt][3]));
        }
        rm0 = fmaxf(rm0, __shfl_xor_sync(0xffffffffu, rm0, 1));
        rm0 = fmaxf(rm0, __shfl_xor_sync(0xffffffffu, rm0, 2));
        rm1 = fmaxf(rm1, __shfl_xor_sync(0xffffffffu, rm1, 1));
        rm1 = fmaxf(rm1, __shfl_xor_sync(0xffffffffu, rm1, 2));
        float mn0 = fmaxf(m0, rm0), mn1 = fmaxf(m1, rm1);
        float c0 = __expf(m0 - mn0), c1 = __expf(m1 - mn1);
        float p[4][4];
        float s0 = 0.f, s1 = 0.f;
#pragma unroll
        for (int nt = 0; nt < 4; nt++) {
            p[nt][0] = __expf(sacc[nt][0] - mn0);
            p[nt][1] = __expf(sacc[nt][1] - mn0);
            p[nt][2] = __expf(sacc[nt][2] - mn1);
            p[nt][3] = __expf(sacc[nt][3] - mn1);
            s0 += p[nt][0] + p[nt][1];
            s1 += p[nt][2] + p[nt][3];
        }
        s0 += __shfl_xor_sync(0xffffffffu, s0, 1);
        s0 += __shfl_xor_sync(0xffffffffu, s0, 2);
        s1 += __shfl_xor_sync(0xffffffffu, s1, 1);
        s1 += __shfl_xor_sync(0xffffffffu, s1, 2);
        l0 = l0 * c0 + s0; l1 = l1 * c1 + s1;
        m0 = mn0; m1 = mn1;
#pragma unroll
        for (int nt = 0; nt < 8; nt++) {
            oacc[nt][0] *= c0; oacc[nt][1] *= c0;
            oacc[nt][2] *= c1; oacc[nt][3] *= c1;
        }

#pragma unroll
        for (int j = 0; j < 2; j++) {
            uint32_t ph[4], pl[4];
            pack_hl(p[2 * j][0],     p[2 * j][1],     ph[0], pl[0]);
            pack_hl(p[2 * j][2],     p[2 * j][3],     ph[1], pl[1]);
            pack_hl(p[2 * j + 1][0], p[2 * j + 1][1], ph[2], pl[2]);
            pack_hl(p[2 * j + 1][2], p[2 * j + 1][3], ph[3], pl[3]);
#pragma unroll
            for (int ntp = 0; ntp < 4; ntp++) {
                uint32_t ad = vfb[s] + (uint32_t)(j * 16 * 144) + ntp * 32;
                uint32_t vh4[4], vl4[4];
                ldsm4t(vh4, ad);
                ldsm4t(vl4, ad + 4608);
                mma16816(oacc[2*ntp],   ph, vh4);
                mma16816(oacc[2*ntp],   pl, vh4);
                mma16816(oacc[2*ntp],   ph, vl4);
                mma16816(oacc[2*ntp+1], ph, vh4 + 2);
                mma16816(oacc[2*ntp+1], pl, vh4 + 2);
                mma16816(oacc[2*ntp+1], ph, vl4 + 2);
            }
        }
        __syncthreads();
    }

    float il0 = 1.f / l0, il1 = 1.f / l1;
    int g = lane >> 2, cc2 = (lane & 3) * 2;
    int row0 = b * TQ + qt * 64 + warp * 16 + g;
#pragma unroll
    for (int nt = 0; nt < 8; nt++) {
        int col = h * HD + nt * 8 + cc2;
        float2 v0 = make_float2(oacc[nt][0] * il0, oacc[nt][1] * il0);
        float2 v1 = make_float2(oacc[nt][2] * il1, oacc[nt][3] * il1);
        *(float2*)&g_att[(size_t)row0 * DMODEL + col] = v0;
        *(float2*)&g_att[(size_t)(row0 + 8) * DMODEL + col] = v1;
    }
}

// ---------------------------------------------------------------------------
extern "C" void kernel_launch(void* const* d_in, const int* in_sizes, int n_in,
                              void* d_out, int out_size)
{
    const float *x = 0, *w_qkv = 0, *w_out = 0, *b_out = 0;
    for (int i = 0; i < n_in; i++) {
        switch (in_sizes[i]) {
            case 4194304: x     = (const float*)d_in[i]; break;
            case 3145728: w_qkv = (const float*)d_in[i]; break;
            case 1048576: w_out = (const float*)d_in[i]; break;
            case 1024:    b_out = (const float*)d_in[i]; break;
        }
    }
    if (!x && n_in >= 4) {
        x     = (const float*)d_in[0];
        w_qkv = (const float*)d_in[1];
        w_out = (const float*)d_in[2];
        b_out = (const float*)d_in[3];
    }
    float* out = (float*)d_out;

    fill_qkv_kernel<<<4096, 256>>>();
    rope_table_kernel<<<(TQ * 32 + 255) / 256, 256>>>();
    // 1) g_qkv = x @ w_qkv^T
    gemm_nt_bf16x3<<<dim3(D3 / 128, BT / 128), 256>>>(
        x, w_qkv, nullptr, nullptr, BT, D3, DMODEL, 0, 1);
    // 2) Fused RoPE + KV hi/lo convert
    rope_kv_kernel<<<BT, 256>>>();
    // 3) attention
    flash_tc_kernel<<<dim3(32, 32), 128>>>();
    // 4) out = g_att @ w_out^T + b_out
    gemm_nt_bf16x3<<<dim3(DMODEL / 128, BT / 128), 256>>>(
        nullptr, w_out, b_out, out, BT, DMODEL, DMODEL, 1, 0);
}